// round 8
// baseline (speedup 1.0000x reference)
#include <cuda_runtime.h>
#include <cstdint>

// Problem constants: N=200000 nodes, D=256 features, G=512 graphs.
#define D 256
#define G 512
#define GPB 16                 // graphs per block-tile in GEMM
#define KPB 32                 // k-values per block-slice in GEMM
#define RPB 128                // rows per block in segsum

__device__ int   g_layout;         // 0 = int32 indices, 1 = int64 indices
__device__ float g_sum[G * D];     // pooled features
__device__ float g_acc[G * D];     // split-K accumulator (pre-bias, pre-relu)

__device__ __forceinline__ int load_idx(const int* __restrict__ raw, int i, int layout)
{
    return layout ? raw[2 * i] : raw[i];
}

// ---------------------------------------------------------------------------
// Kernel 1: zero g_sum/g_acc (every replay) and detect index storage layout
// from the LAST 256 int32 words (batch_idx sorted: int32 => odd words
// nonzero; int64 (<2^32) => odd zero, even nonzero; all-zero => either).
// ---------------------------------------------------------------------------
__global__ void k_init(const int* __restrict__ raw, int n)
{
    int i = blockIdx.x * blockDim.x + threadIdx.x;
    g_sum[i] = 0.0f;
    g_acc[i] = 0.0f;

    if (blockIdx.x == 0) {
        int w = n - 256 + threadIdx.x;
        int odd_nz = 0, even_nz = 0;
        if (w >= 0) {
            int v = raw[w];
            if (v != 0) {
                if (w & 1) odd_nz = 1; else even_nz = 1;
            }
        }
        int o = __syncthreads_or(odd_nz);
        int e = __syncthreads_or(even_nz);
        if (threadIdx.x == 0)
            g_layout = o ? 0 : (e ? 1 : 0);
    }
}

// ---------------------------------------------------------------------------
// Kernel 2: segment sum, MLP-batched (R7 form, measured ~32us = BW floor).
// Block owns RPB=128 contiguous rows; 64 column-quads x 4 row-stripes.
// Chunks of 8 rows: batch the 8 independent float4 loads (MLP=8), then run
// segment logic on registers; atomic flush only on boundaries.
// ---------------------------------------------------------------------------
__global__ void __launch_bounds__(256) k_segsum(const float* __restrict__ h,
                                                const int* __restrict__ raw, int n)
{
    __shared__ int sidx[RPB];
    int layout = g_layout;
    int r0 = blockIdx.x * RPB;
    if (threadIdx.x < RPB) {
        int r = r0 + threadIdx.x;
        sidx[threadIdx.x] = (r < n) ? load_idx(raw, r, layout) : -1;
    }
    __syncthreads();

    int tx = threadIdx.x & 63;
    int ty = threadIdx.x >> 6;

    float4 acc = make_float4(0.f, 0.f, 0.f, 0.f);
    int cur = -1;

#pragma unroll
    for (int base = 0; base < RPB; base += 32) {
        float4 v[8];
#pragma unroll
        for (int j = 0; j < 8; j++) {
            int row = r0 + base + ty + j * 4;
            if (row < n)
                v[j] = *reinterpret_cast<const float4*>(h + (size_t)row * D + tx * 4);
            else
                v[j] = make_float4(0.f, 0.f, 0.f, 0.f);
        }
#pragma unroll
        for (int j = 0; j < 8; j++) {
            int rr = base + ty + j * 4;
            if (r0 + rr >= n) break;
            int seg = sidx[rr];
            if (seg != cur) {
                if (cur >= 0) {
                    float* dst = &g_sum[cur * D + tx * 4];
                    atomicAdd(dst + 0, acc.x);
                    atomicAdd(dst + 1, acc.y);
                    atomicAdd(dst + 2, acc.z);
                    atomicAdd(dst + 3, acc.w);
                }
                acc = make_float4(0.f, 0.f, 0.f, 0.f);
                cur = seg;
            }
            acc.x += v[j].x; acc.y += v[j].y; acc.z += v[j].z; acc.w += v[j].w;
        }
    }
    if (cur >= 0) {
        float* dst = &g_sum[cur * D + tx * 4];
        atomicAdd(dst + 0, acc.x);
        atomicAdd(dst + 1, acc.y);
        atomicAdd(dst + 2, acc.z);
        atomicAdd(dst + 3, acc.w);
    }
}

// ---------------------------------------------------------------------------
// Kernel 3: split-K GEMM with KPB=32 (halved atomic count vs R7: 1M scalar
// REDGs instead of 2M). grid (G/GPB, D/KPB) = (32, 8) = 256 blocks; thread
// t owns column t for GPB graphs over KPB k's.
// ---------------------------------------------------------------------------
__global__ void __launch_bounds__(256) k_gemm_splitk(const float* __restrict__ W)
{
    __shared__ float s[GPB][KPB];
    int g0 = blockIdx.x * GPB;
    int k0 = blockIdx.y * KPB;
    int t  = threadIdx.x;

    // 256 threads load GPB*KPB = 512 pooled values (2 each, coalesced pairs)
    {
        int j = t;
        s[j >> 5][j & 31] = g_sum[(g0 + (j >> 5)) * D + (k0 + (j & 31))];
        j = t + 256;
        s[j >> 5][j & 31] = g_sum[(g0 + (j >> 5)) * D + (k0 + (j & 31))];
    }
    __syncthreads();

    float acc[GPB];
#pragma unroll
    for (int r = 0; r < GPB; r++) acc[r] = 0.0f;

#pragma unroll 8
    for (int kk = 0; kk < KPB; kk++) {
        float w = __ldg(&W[(k0 + kk) * D + t]);
#pragma unroll
        for (int r = 0; r < GPB; r++)
            acc[r] = fmaf(s[r][kk], w, acc[r]);
    }

#pragma unroll
    for (int r = 0; r < GPB; r++)
        atomicAdd(&g_acc[(g0 + r) * D + t], acc[r]);
}

// ---------------------------------------------------------------------------
// Kernel 4: out = relu(g_acc[seg] + b) + h. Reverse row order harvests the
// L2 tail left by k_segsum; misses evict-first. Bias+relu fused here
// (costs ~2.3us here vs ~5us as a standalone kernel).
// ---------------------------------------------------------------------------
__global__ void k_out(const float* __restrict__ h, const int* __restrict__ raw,
                      const float* __restrict__ b, float* __restrict__ out, int n)
{
    int layout = g_layout;
    int gt = blockIdx.x * blockDim.x + threadIdx.x;   // one thread per 2 quads
    int ridx = gt >> 5;
    if (ridx >= n) return;
    int i = n - 1 - ridx;     // reverse row order
    int q = (gt & 31) * 2;
    int seg = load_idx(raw, i, layout);

    const float4* hp = reinterpret_cast<const float4*>(h + (size_t)i * D) + q;
    const float4 a0 = __ldcs(hp);
    const float4 a1 = __ldcs(hp + 1);
    const float4* vp = reinterpret_cast<const float4*>(g_acc + seg * D) + q;
    const float4 v0 = vp[0];
    const float4 v1 = vp[1];
    const float4* bp = reinterpret_cast<const float4*>(b) + q;
    const float4 b0 = bp[0];
    const float4 b1 = bp[1];

    float4 r0, r1;
    r0.x = fmaxf(v0.x + b0.x, 0.0f) + a0.x;
    r0.y = fmaxf(v0.y + b0.y, 0.0f) + a0.y;
    r0.z = fmaxf(v0.z + b0.z, 0.0f) + a0.z;
    r0.w = fmaxf(v0.w + b0.w, 0.0f) + a0.w;
    r1.x = fmaxf(v1.x + b1.x, 0.0f) + a1.x;
    r1.y = fmaxf(v1.y + b1.y, 0.0f) + a1.y;
    r1.z = fmaxf(v1.z + b1.z, 0.0f) + a1.z;
    r1.w = fmaxf(v1.w + b1.w, 0.0f) + a1.w;

    float4* op = reinterpret_cast<float4*>(out + (size_t)i * D) + q;
    __stcs(op, r0);
    __stcs(op + 1, r1);
}

extern "C" void kernel_launch(void* const* d_in, const int* in_sizes, int n_in,
                              void* d_out, int out_size)
{
    const float* h   = (const float*)d_in[0];
    const int*   raw = (const int*)  d_in[1];
    const float* W   = (const float*)d_in[2];
    const float* b   = (const float*)d_in[3];
    float* out = (float*)d_out;

    const int n  = in_sizes[1];
    const int nbs = (n + RPB - 1) / RPB;

    k_init  <<<G * D / 256, 256>>>(raw, n);
    k_segsum<<<nbs, 256>>>(h, raw, n);
    k_gemm_splitk<<<dim3(G / GPB, D / KPB), 256>>>(W);
    {
        long long tt = (long long)n * 32;   // one thread per 2 float4
        int blocks = (int)((tt + 255) / 256);
        k_out<<<blocks, 256>>>(h, raw, b, out, n);
    }
}

// round 9
// speedup vs baseline: 1.0328x; 1.0328x over previous
#include <cuda_runtime.h>
#include <cstdint>

// Problem constants: N=200000 nodes, D=256 features, G=512 graphs.
#define D 256
#define G 512
#define GPB 16                 // graphs per block-tile in GEMM
#define KPB 16                 // k-values per block-slice in GEMM
#define RPB 128                // rows per block in segsum

__device__ int   g_layout;         // 0 = int32 indices, 1 = int64 indices
__device__ float g_sum[G * D];     // pooled features
__device__ float g_acc[G * D];     // split-K accumulator (pre-bias, pre-relu)

__device__ __forceinline__ int load_idx(const int* __restrict__ raw, int i, int layout)
{
    return layout ? raw[2 * i] : raw[i];
}

// ---------------------------------------------------------------------------
// Kernel 1: zero g_sum/g_acc (every replay) and detect index storage layout
// from the LAST 256 int32 words (batch_idx sorted: int32 => odd words
// nonzero; int64 (<2^32) => odd zero, even nonzero; all-zero => either).
// ---------------------------------------------------------------------------
__global__ void k_init(const int* __restrict__ raw, int n)
{
    int i = blockIdx.x * blockDim.x + threadIdx.x;
    g_sum[i] = 0.0f;
    g_acc[i] = 0.0f;

    if (blockIdx.x == 0) {
        int w = n - 256 + threadIdx.x;
        int odd_nz = 0, even_nz = 0;
        if (w >= 0) {
            int v = raw[w];
            if (v != 0) {
                if (w & 1) odd_nz = 1; else even_nz = 1;
            }
        }
        int o = __syncthreads_or(odd_nz);
        int e = __syncthreads_or(even_nz);
        if (threadIdx.x == 0)
            g_layout = o ? 0 : (e ? 1 : 0);
    }
}

// ---------------------------------------------------------------------------
// Kernel 2: segment sum, MLP-batched (measured ~32us = BW floor).
// Block owns RPB=128 contiguous rows; 64 column-quads x 4 row-stripes.
// Chunks of 8 rows: batch the 8 independent float4 loads (MLP=8), then run
// segment logic on registers; atomic flush only on boundaries.
// ---------------------------------------------------------------------------
__global__ void __launch_bounds__(256) k_segsum(const float* __restrict__ h,
                                                const int* __restrict__ raw, int n)
{
    __shared__ int sidx[RPB];
    int layout = g_layout;
    int r0 = blockIdx.x * RPB;
    if (threadIdx.x < RPB) {
        int r = r0 + threadIdx.x;
        sidx[threadIdx.x] = (r < n) ? load_idx(raw, r, layout) : -1;
    }
    __syncthreads();

    int tx = threadIdx.x & 63;
    int ty = threadIdx.x >> 6;

    float4 acc = make_float4(0.f, 0.f, 0.f, 0.f);
    int cur = -1;

#pragma unroll
    for (int base = 0; base < RPB; base += 32) {
        float4 v[8];
#pragma unroll
        for (int j = 0; j < 8; j++) {
            int row = r0 + base + ty + j * 4;
            if (row < n)
                v[j] = *reinterpret_cast<const float4*>(h + (size_t)row * D + tx * 4);
            else
                v[j] = make_float4(0.f, 0.f, 0.f, 0.f);
        }
#pragma unroll
        for (int j = 0; j < 8; j++) {
            int rr = base + ty + j * 4;
            if (r0 + rr >= n) break;
            int seg = sidx[rr];
            if (seg != cur) {
                if (cur >= 0) {
                    float* dst = &g_sum[cur * D + tx * 4];
                    atomicAdd(dst + 0, acc.x);
                    atomicAdd(dst + 1, acc.y);
                    atomicAdd(dst + 2, acc.z);
                    atomicAdd(dst + 3, acc.w);
                }
                acc = make_float4(0.f, 0.f, 0.f, 0.f);
                cur = seg;
            }
            acc.x += v[j].x; acc.y += v[j].y; acc.z += v[j].z; acc.w += v[j].w;
        }
    }
    if (cur >= 0) {
        float* dst = &g_sum[cur * D + tx * 4];
        atomicAdd(dst + 0, acc.x);
        atomicAdd(dst + 1, acc.y);
        atomicAdd(dst + 2, acc.z);
        atomicAdd(dst + 3, acc.w);
    }
}

// ---------------------------------------------------------------------------
// Kernel 3: split-K GEMM, exact R7 form (measured 7.9us). grid
// (G/GPB, D/KPB) = (32, 16) = 512 blocks; thread t owns column t for GPB
// graphs over KPB k's; W loads batched up-front; scalar atomic accumulate.
// ---------------------------------------------------------------------------
__global__ void __launch_bounds__(256) k_gemm_splitk(const float* __restrict__ W)
{
    __shared__ float s[GPB][KPB];
    int g0 = blockIdx.x * GPB;
    int k0 = blockIdx.y * KPB;
    int t  = threadIdx.x;

    float w[KPB];
#pragma unroll
    for (int kk = 0; kk < KPB; kk++)
        w[kk] = __ldg(&W[(k0 + kk) * D + t]);

    {
        int r  = t >> 4;
        int kk = t & 15;
        s[r][kk] = g_sum[(g0 + r) * D + (k0 + kk)];
    }
    __syncthreads();

    float acc[GPB];
#pragma unroll
    for (int r = 0; r < GPB; r++) acc[r] = 0.0f;

#pragma unroll
    for (int kk = 0; kk < KPB; kk++) {
#pragma unroll
        for (int r = 0; r < GPB; r++)
            acc[r] = fmaf(s[r][kk], w[kk], acc[r]);
    }

#pragma unroll
    for (int r = 0; r < GPB; r++)
        atomicAdd(&g_acc[(g0 + r) * D + t], acc[r]);
}

// ---------------------------------------------------------------------------
// Kernel 4: out = relu(g_acc[seg] + b) + h (R8 fused form, measured
// 64.6us; replaces the 4.96us standalone bias kernel for a net win).
// Reverse row order harvests the L2 tail left by k_segsum; misses
// evict-first.
// ---------------------------------------------------------------------------
__global__ void k_out(const float* __restrict__ h, const int* __restrict__ raw,
                      const float* __restrict__ b, float* __restrict__ out, int n)
{
    int layout = g_layout;
    int gt = blockIdx.x * blockDim.x + threadIdx.x;   // one thread per 2 quads
    int ridx = gt >> 5;
    if (ridx >= n) return;
    int i = n - 1 - ridx;     // reverse row order
    int q = (gt & 31) * 2;
    int seg = load_idx(raw, i, layout);

    const float4* hp = reinterpret_cast<const float4*>(h + (size_t)i * D) + q;
    const float4 a0 = __ldcs(hp);
    const float4 a1 = __ldcs(hp + 1);
    const float4* vp = reinterpret_cast<const float4*>(g_acc + seg * D) + q;
    const float4 v0 = vp[0];
    const float4 v1 = vp[1];
    const float4* bp = reinterpret_cast<const float4*>(b) + q;
    const float4 b0 = bp[0];
    const float4 b1 = bp[1];

    float4 r0, r1;
    r0.x = fmaxf(v0.x + b0.x, 0.0f) + a0.x;
    r0.y = fmaxf(v0.y + b0.y, 0.0f) + a0.y;
    r0.z = fmaxf(v0.z + b0.z, 0.0f) + a0.z;
    r0.w = fmaxf(v0.w + b0.w, 0.0f) + a0.w;
    r1.x = fmaxf(v1.x + b1.x, 0.0f) + a1.x;
    r1.y = fmaxf(v1.y + b1.y, 0.0f) + a1.y;
    r1.z = fmaxf(v1.z + b1.z, 0.0f) + a1.z;
    r1.w = fmaxf(v1.w + b1.w, 0.0f) + a1.w;

    float4* op = reinterpret_cast<float4*>(out + (size_t)i * D) + q;
    __stcs(op, r0);
    __stcs(op + 1, r1);
}

extern "C" void kernel_launch(void* const* d_in, const int* in_sizes, int n_in,
                              void* d_out, int out_size)
{
    const float* h   = (const float*)d_in[0];
    const int*   raw = (const int*)  d_in[1];
    const float* W   = (const float*)d_in[2];
    const float* b   = (const float*)d_in[3];
    float* out = (float*)d_out;

    const int n  = in_sizes[1];
    const int nbs = (n + RPB - 1) / RPB;

    k_init  <<<G * D / 256, 256>>>(raw, n);
    k_segsum<<<nbs, 256>>>(h, raw, n);
    k_gemm_splitk<<<dim3(G / GPB, D / KPB), 256>>>(W);
    {
        long long tt = (long long)n * 32;   // one thread per 2 float4
        int blocks = (int)((tt + 255) / 256);
        k_out<<<blocks, 256>>>(h, raw, b, out, n);
    }
}